// round 8
// baseline (speedup 1.0000x reference)
#include <cuda_runtime.h>
#include <math.h>

// Problem: input (8, 64, 64, 3) fp32 -> scalar fp32.
#define NB   8
#define NPIX 4096            // 64*64
#define NELE (NB * NPIX)     // 32768
#define PRE_BLKS 64
#define MAIN_BLKS 1088       // symmetric block set (see c_off)

// ---- scratch (no allocations allowed -> __device__ globals) ----
__device__ __align__(16) float g_a[NELE];        // |x|.sum(-1), layout [b][i]
__device__ __align__(16) float g_t[NELE];        // same values, pixel-major [i][b]
__device__ float        g_bmin[PRE_BLKS];
__device__ float        g_bmax[PRE_BLKS];
__device__ float        g_inv, g_nb;             // f = fma(a, inv, nb)
__device__ double       g_part[MAIN_BLKS];
__device__ unsigned int g_cnt_pre  = 0;          // self-resetting counters
__device__ unsigned int g_cnt_main = 0;

// i-tile = 4 rows (bx 0..15). For each bx, jy in [4bx, 64), 2 chunks of 32 j.
// c_off[bx+1] = c_off[bx] + 2*(64-4*bx)
__constant__ int c_off[17] = {0, 128, 248, 360, 464, 560, 648, 728, 800,
                              864, 920, 968, 1008, 1040, 1064, 1080, 1088};

// ---- packed f32x2 helpers (Blackwell FFMA2 — only reachable via PTX) ----
__device__ __forceinline__ unsigned long long pk2(float lo, float hi) {
    unsigned long long r;
    asm("mov.b64 %0, {%1,%2};" : "=l"(r) : "f"(lo), "f"(hi));
    return r;
}
__device__ __forceinline__ void unpk2(unsigned long long v, float& lo, float& hi) {
    asm("mov.b64 {%0,%1}, %2;" : "=f"(lo), "=f"(hi) : "l"(v));
}
__device__ __forceinline__ unsigned long long mul2(unsigned long long a, unsigned long long b) {
    unsigned long long r;
    asm("mul.rn.f32x2 %0, %1, %2;" : "=l"(r) : "l"(a), "l"(b));
    return r;
}
__device__ __forceinline__ unsigned long long fma2(unsigned long long a, unsigned long long b,
                                                   unsigned long long c) {
    unsigned long long r;
    asm("fma.rn.f32x2 %0, %1, %2, %3;" : "=l"(r) : "l"(a), "l"(b), "l"(c));
    return r;
}

// ---------------------------------------------------------------
// 4 pixels/thread (3 x LDG.128). Writes g_a (batch-major, STG.128), g_t
// (pixel-major, 4 scattered STG.32), per-block min/max; last block finishes
// the min/max reduction and publishes (inv, nb).
__global__ void __launch_bounds__(128) k_pre(const float4* __restrict__ in4) {
    int t = blockIdx.x * 128 + threadIdx.x;            // 0..8191
    float4 a = in4[t * 3 + 0];
    float4 b = in4[t * 3 + 1];
    float4 c = in4[t * 3 + 2];

    float4 s;
    s.x = fabsf(a.x) + fabsf(a.y) + fabsf(a.z);
    s.y = fabsf(a.w) + fabsf(b.x) + fabsf(b.y);
    s.z = fabsf(b.z) + fabsf(b.w) + fabsf(c.x);
    s.w = fabsf(c.y) + fabsf(c.z) + fabsf(c.w);
    *(float4*)&g_a[t * 4] = s;

    int bb = t >> 10;                                  // batch of this thread
    int p0 = (t & 1023) * 4;                           // first pixel
    g_t[(p0 + 0) * 8 + bb] = s.x;
    g_t[(p0 + 1) * 8 + bb] = s.y;
    g_t[(p0 + 2) * 8 + bb] = s.z;
    g_t[(p0 + 3) * 8 + bb] = s.w;

    float mn = fminf(fminf(s.x, s.y), fminf(s.z, s.w));
    float mx = fmaxf(fmaxf(s.x, s.y), fmaxf(s.z, s.w));
    #pragma unroll
    for (int o = 16; o; o >>= 1) {
        mn = fminf(mn, __shfl_xor_sync(0xffffffffu, mn, o));
        mx = fmaxf(mx, __shfl_xor_sync(0xffffffffu, mx, o));
    }
    __shared__ float smn[4], smx[4];
    __shared__ bool  s_last;
    int wid = threadIdx.x >> 5, lid = threadIdx.x & 31;
    if (lid == 0) { smn[wid] = mn; smx[wid] = mx; }
    __syncthreads();
    if (threadIdx.x == 0) {
        #pragma unroll
        for (int w = 1; w < 4; w++) { mn = fminf(mn, smn[w]); mx = fmaxf(mx, smx[w]); }
        g_bmin[blockIdx.x] = mn;
        g_bmax[blockIdx.x] = mx;
        __threadfence();
        s_last = (atomicAdd(&g_cnt_pre, 1u) == PRE_BLKS - 1u);
    }
    __syncthreads();
    if (s_last && threadIdx.x < 64) {
        float m2 = ((volatile float*)g_bmin)[threadIdx.x];
        float x2 = ((volatile float*)g_bmax)[threadIdx.x];
        #pragma unroll
        for (int o = 16; o; o >>= 1) {
            m2 = fminf(m2, __shfl_xor_sync(0xffffffffu, m2, o));
            x2 = fmaxf(x2, __shfl_xor_sync(0xffffffffu, x2, o));
        }
        if (threadIdx.x == 0)  { smn[0] = m2; }
        if (threadIdx.x == 32) { smx[0] = x2; }
        __syncwarp();
        if (threadIdx.x == 0) {
            // wait: need both warps' results; warp1 wrote smx via syncwarp only.
        }
    }
    if (s_last) {
        __syncthreads();
        if (threadIdx.x == 0) {
            float mnF = smn[0], mxF = smx[0];
            float inv = 1.0f / (mxF - mnF);
            g_inv = inv;
            g_nb  = -mnF * inv;
            g_cnt_pre = 0;                              // reset for graph replay
        }
    }
}

// ---------------------------------------------------------------
// Symmetric main kernel. Block = (i-tile of 4 rows) x (32-j chunk).
// Pair weight {0,1,2} folded into the distance table.
// One pixel per thread: i = bx*256 + tid (local row r = tid>>6).
__global__ void __launch_bounds__(256) k_main(float* __restrict__ out) {
    __shared__ float  s_dist[256];                     // [r 0..3][dx 0..63], weighted
    __shared__ __align__(16) float s_fj[256];          // 32 j x 8 b, pixel-major
    __shared__ double s_red[8];
    __shared__ bool   s_last;

    int tid  = threadIdx.x;
    int lane = tid & 31, wid = tid >> 5;

    // ---- decode (bx, jy, jlo) ----
    int bid = blockIdx.x;
    int bx = 0;
    #pragma unroll
    for (int t = 1; t < 16; t++) bx += (bid >= c_off[t]);
    int rel = bid - c_off[bx];
    int jy  = 4 * bx + (rel >> 1);
    int jlo = (rel & 1) << 5;
    int ry0 = bx * 4;

    float inv = g_inv;
    float nb  = g_nb;

    // ---- weighted distance table: one entry per thread ----
    {
        int r  = tid >> 6, dx = tid & 63;
        int ry = ry0 + r;
        int dy = jy - ry;
        float w = (dy > 0) ? 2.0f : (dy == 0 ? 1.0f : 0.0f);
        s_dist[tid] = w * sqrtf((float)(dy * dy + dx * dx));
    }

    // ---- normalized f of the 32-j chunk (coalesced from batch-major) ----
    {
        int b = tid >> 5, x = tid & 31;                // warp b loads 128B run
        s_fj[x * 8 + b] = fmaf(g_a[b * NPIX + jy * 64 + jlo + x], inv, nb);
    }

    // ---- this thread's pixel, 2 x LDG.128 from pixel-major mirror ----
    int i = bx * 256 + tid;
    unsigned long long fi[4];
    {
        float4 lo = *(const float4*)&g_t[i * 8];
        float4 hi = *(const float4*)&g_t[i * 8 + 4];
        fi[0] = pk2(fmaf(lo.x, inv, nb), fmaf(lo.y, inv, nb));
        fi[1] = pk2(fmaf(lo.z, inv, nb), fmaf(lo.w, inv, nb));
        fi[2] = pk2(fmaf(hi.x, inv, nb), fmaf(hi.y, inv, nb));
        fi[3] = pk2(fmaf(hi.z, inv, nb), fmaf(hi.w, inv, nb));
    }
    __syncthreads();

    int ix = tid & 63;
    const float* drow = s_dist + ((tid >> 6) << 6);
    int jx0 = jlo;

    unsigned long long acc0 = 0ull, acc1 = 0ull;       // independent chains
    #pragma unroll 4
    for (int jj = 0; jj < 32; jj += 2) {
        // even jj
        {
            ulonglong2 ja = *(const ulonglong2*)(s_fj + jj * 8);
            ulonglong2 jb = *(const ulonglong2*)(s_fj + jj * 8 + 4);
            int m = ix - (jx0 + jj); m = m < 0 ? -m : m;
            float d = drow[m];
            unsigned long long p = mul2(fi[0], ja.x);
            p = fma2(fi[1], ja.y, p);
            p = fma2(fi[2], jb.x, p);
            p = fma2(fi[3], jb.y, p);
            acc0 = fma2(p, pk2(d, d), acc0);
        }
        // odd jj
        {
            ulonglong2 ja = *(const ulonglong2*)(s_fj + (jj + 1) * 8);
            ulonglong2 jb = *(const ulonglong2*)(s_fj + (jj + 1) * 8 + 4);
            int m = ix - (jx0 + jj + 1); m = m < 0 ? -m : m;
            float d = drow[m];
            unsigned long long q = mul2(fi[0], ja.x);
            q = fma2(fi[1], ja.y, q);
            q = fma2(fi[2], jb.x, q);
            q = fma2(fi[3], jb.y, q);
            acc1 = fma2(q, pk2(d, d), acc1);
        }
    }

    float a0, a1, b0, b1;
    unpk2(acc0, a0, a1);
    unpk2(acc1, b0, b1);
    double dacc = ((double)a0 + (double)a1) + ((double)b0 + (double)b1);
    #pragma unroll
    for (int o = 16; o; o >>= 1)
        dacc += __shfl_xor_sync(0xffffffffu, dacc, o);
    if (lane == 0) s_red[wid] = dacc;
    __syncthreads();
    if (tid == 0) {
        double s = s_red[0];
        #pragma unroll
        for (int w = 1; w < 8; w++) s += s_red[w];
        g_part[bid] = s;
        __threadfence();
        s_last = (atomicAdd(&g_cnt_main, 1u) == (MAIN_BLKS - 1u));
    }
    __syncthreads();

    // ---- last block reduces all partials (fixed order -> deterministic) ----
    if (s_last) {
        double s = 0.0;
        for (int k = tid; k < MAIN_BLKS; k += 256)
            s += ((volatile double*)g_part)[k];
        #pragma unroll
        for (int o = 16; o; o >>= 1)
            s += __shfl_xor_sync(0xffffffffu, s, o);
        if (lane == 0) s_red[wid] = s;
        __syncthreads();
        if (tid == 0) {
            double t = s_red[0];
            #pragma unroll
            for (int w = 1; w < 8; w++) t += s_red[w];
            out[0] = (float)(t / 134217728.0);          // / (B*N*N)
            g_cnt_main = 0;                             // reset for graph replay
        }
    }
}

extern "C" void kernel_launch(void* const* d_in, const int* in_sizes, int n_in,
                              void* d_out, int out_size) {
    const float4* in4 = (const float4*)d_in[0];
    float*        out = (float*)d_out;

    k_pre<<<PRE_BLKS, 128>>>(in4);
    k_main<<<MAIN_BLKS, 256>>>(out);
}

// round 9
// speedup vs baseline: 1.3662x; 1.3662x over previous
#include <cuda_runtime.h>
#include <math.h>

// Problem: input (8, 64, 64, 3) fp32 -> scalar fp32.
#define NB   8
#define NPIX 4096            // 64*64
#define NELE (NB * NPIX)     // 32768
#define PRE_BLKS 64
#define MAIN_BLKS 288        // triangular block set (see c_off)

// ---- scratch (no allocations allowed -> __device__ globals) ----
__device__ __align__(16) float g_a[NELE];        // |x|.sum(-1), layout [b][i]
__device__ __align__(16) float g_t[NELE];        // same values, pixel-major [i][b]
__device__ float        g_bmin[PRE_BLKS];
__device__ float        g_bmax[PRE_BLKS];
__device__ float        g_inv, g_nb;             // f = fma(a, inv, nb)
__device__ double       g_part[MAIN_BLKS];
__device__ unsigned int g_cnt_pre  = 0;          // self-resetting counters
__device__ unsigned int g_cnt_main = 0;

// i-tile = 8 rows (bx 0..7). For each bx, jy in [8bx, 64) -> 64-8bx blocks.
__constant__ int c_off[9] = {0, 64, 120, 168, 208, 240, 264, 280, 288};

// ---- packed f32x2 helpers (Blackwell FFMA2 — only reachable via PTX) ----
__device__ __forceinline__ unsigned long long pk2(float lo, float hi) {
    unsigned long long r;
    asm("mov.b64 %0, {%1,%2};" : "=l"(r) : "f"(lo), "f"(hi));
    return r;
}
__device__ __forceinline__ void unpk2(unsigned long long v, float& lo, float& hi) {
    asm("mov.b64 {%0,%1}, %2;" : "=f"(lo), "=f"(hi) : "l"(v));
}
__device__ __forceinline__ unsigned long long mul2(unsigned long long a, unsigned long long b) {
    unsigned long long r;
    asm("mul.rn.f32x2 %0, %1, %2;" : "=l"(r) : "l"(a), "l"(b));
    return r;
}
__device__ __forceinline__ unsigned long long fma2(unsigned long long a, unsigned long long b,
                                                   unsigned long long c) {
    unsigned long long r;
    asm("fma.rn.f32x2 %0, %1, %2, %3;" : "=l"(r) : "l"(a), "l"(b), "l"(c));
    return r;
}

// ---------------------------------------------------------------
// 4 pixels/thread (3 x LDG.128). Writes g_a (batch-major), g_t (pixel-major),
// per-block min/max; last block finishes min/max and publishes (inv, nb).
__global__ void __launch_bounds__(128) k_pre(const float4* __restrict__ in4) {
    int t = blockIdx.x * 128 + threadIdx.x;            // 0..8191
    float4 a = in4[t * 3 + 0];
    float4 b = in4[t * 3 + 1];
    float4 c = in4[t * 3 + 2];

    float4 s;
    s.x = fabsf(a.x) + fabsf(a.y) + fabsf(a.z);
    s.y = fabsf(a.w) + fabsf(b.x) + fabsf(b.y);
    s.z = fabsf(b.z) + fabsf(b.w) + fabsf(c.x);
    s.w = fabsf(c.y) + fabsf(c.z) + fabsf(c.w);
    *(float4*)&g_a[t * 4] = s;

    int bb = t >> 10;                                  // batch
    int p0 = (t & 1023) * 4;                           // first pixel
    g_t[(p0 + 0) * 8 + bb] = s.x;
    g_t[(p0 + 1) * 8 + bb] = s.y;
    g_t[(p0 + 2) * 8 + bb] = s.z;
    g_t[(p0 + 3) * 8 + bb] = s.w;

    float mn = fminf(fminf(s.x, s.y), fminf(s.z, s.w));
    float mx = fmaxf(fmaxf(s.x, s.y), fmaxf(s.z, s.w));
    #pragma unroll
    for (int o = 16; o; o >>= 1) {
        mn = fminf(mn, __shfl_xor_sync(0xffffffffu, mn, o));
        mx = fmaxf(mx, __shfl_xor_sync(0xffffffffu, mx, o));
    }
    __shared__ float smn[4], smx[4];
    __shared__ bool  s_last;
    int wid = threadIdx.x >> 5, lid = threadIdx.x & 31;
    if (lid == 0) { smn[wid] = mn; smx[wid] = mx; }
    __syncthreads();
    if (threadIdx.x == 0) {
        #pragma unroll
        for (int w = 1; w < 4; w++) { mn = fminf(mn, smn[w]); mx = fmaxf(mx, smx[w]); }
        g_bmin[blockIdx.x] = mn;
        g_bmax[blockIdx.x] = mx;
        __threadfence();
        s_last = (atomicAdd(&g_cnt_pre, 1u) == PRE_BLKS - 1u);
    }
    __syncthreads();
    if (s_last) {
        if (threadIdx.x < 64) {
            float m2 = ((volatile float*)g_bmin)[threadIdx.x];
            float x2 = ((volatile float*)g_bmax)[threadIdx.x];
            #pragma unroll
            for (int o = 16; o; o >>= 1) {
                m2 = fminf(m2, __shfl_xor_sync(0xffffffffu, m2, o));
                x2 = fmaxf(x2, __shfl_xor_sync(0xffffffffu, x2, o));
            }
            if (threadIdx.x == 0)  { smn[0] = m2; smx[1] = x2; }
            if (threadIdx.x == 32) { smx[0] = x2; smn[1] = m2; }
        }
        __syncthreads();
        if (threadIdx.x == 0) {
            float mnF = fminf(smn[0], smn[1]);
            float mxF = fmaxf(smx[0], smx[1]);
            float inv = 1.0f / (mxF - mnF);
            g_inv = inv;
            g_nb  = -mnF * inv;
            g_cnt_pre = 0;                              // reset for graph replay
        }
    }
}

// ---------------------------------------------------------------
// Symmetric main kernel. Block = (i-tile of 8 rows = 512 px) x (full j-row of 64).
// Only jy >= ry0 launched; pair weight {0,1,2} folded into the signed-index
// distance table s_d2[r][ix - jx + 63]. Thread: iA = tile+tid (row r=tid>>6),
// iB = iA+256 (row r+4).
__global__ void __launch_bounds__(256) k_main(float* __restrict__ out) {
    __shared__ __align__(8)  float2 s_d2[512];         // [r 0..3][m 0..127]
    __shared__ __align__(16) float  s_fj[512];         // 64 j x 8 b, pixel-major
    __shared__ double s_red[8];
    __shared__ bool   s_last;

    int tid  = threadIdx.x;
    int lane = tid & 31, wid = tid >> 5;

    // ---- decode (bx, jy) ----
    int bid = blockIdx.x;
    int bx = 0;
    #pragma unroll
    for (int t = 1; t < 8; t++) bx += (bid >= c_off[t]);
    int jy  = (bid - c_off[bx]) + 8 * bx;
    int ry0 = bx * 8;

    float inv = g_inv;
    float nb  = g_nb;

    // ---- weighted signed-index distance table: 2 float2 entries/thread ----
    #pragma unroll
    for (int e = tid; e < 512; e += 256) {
        int r  = e >> 7;                               // row-pair 0..3
        int m  = e & 127;
        int dx = m - 63;                               // ix - jx
        int ry = ry0 + r, ry4 = ry + 4;
        int dy0 = jy - ry, dy1 = jy - ry4;
        float w0 = (dy0 > 0) ? 2.0f : (dy0 == 0 ? 1.0f : 0.0f);
        float w1 = (dy1 > 0) ? 2.0f : (dy1 == 0 ? 1.0f : 0.0f);
        float2 d;
        d.x = w0 * sqrtf((float)(dy0 * dy0 + dx * dx));
        d.y = w1 * sqrtf((float)(dy1 * dy1 + dx * dx));
        s_d2[e] = d;
    }

    // ---- normalized f of the full j row (coalesced from batch-major) ----
    #pragma unroll
    for (int e = tid; e < 512; e += 256) {
        int b = e >> 6, x = e & 63;
        s_fj[x * 8 + b] = fmaf(g_a[b * NPIX + jy * 64 + x], inv, nb);
    }

    // ---- this thread's two pixels from the pixel-major mirror ----
    int iA = bx * 512 + tid;
    int iB = iA + 256;
    unsigned long long fA[4], fB[4];
    {
        float4 lo = *(const float4*)&g_t[iA * 8];
        float4 hi = *(const float4*)&g_t[iA * 8 + 4];
        fA[0] = pk2(fmaf(lo.x, inv, nb), fmaf(lo.y, inv, nb));
        fA[1] = pk2(fmaf(lo.z, inv, nb), fmaf(lo.w, inv, nb));
        fA[2] = pk2(fmaf(hi.x, inv, nb), fmaf(hi.y, inv, nb));
        fA[3] = pk2(fmaf(hi.z, inv, nb), fmaf(hi.w, inv, nb));
        float4 lo2 = *(const float4*)&g_t[iB * 8];
        float4 hi2 = *(const float4*)&g_t[iB * 8 + 4];
        fB[0] = pk2(fmaf(lo2.x, inv, nb), fmaf(lo2.y, inv, nb));
        fB[1] = pk2(fmaf(lo2.z, inv, nb), fmaf(lo2.w, inv, nb));
        fB[2] = pk2(fmaf(hi2.x, inv, nb), fmaf(hi2.y, inv, nb));
        fB[3] = pk2(fmaf(hi2.z, inv, nb), fmaf(hi2.w, inv, nb));
    }
    __syncthreads();

    int ix = tid & 63;
    // row-pair table for local row r = tid>>6; signed index m = ix - jj + 63
    const float2* dbase = s_d2 + ((tid >> 6) << 7) + (ix + 63);

    unsigned long long acc0 = 0ull, acc1 = 0ull;       // A and B chains
    #pragma unroll 16
    for (int jj = 0; jj < 64; jj++) {
        ulonglong2 ja = *(const ulonglong2*)(s_fj + jj * 8);      // b 0..3
        ulonglong2 jb = *(const ulonglong2*)(s_fj + jj * 8 + 4);  // b 4..7
        float2 d = dbase[-jj];                          // one LDS.64, imm offset

        unsigned long long p = mul2(fA[0], ja.x);       // lanes: even-b / odd-b
        p = fma2(fA[1], ja.y, p);
        p = fma2(fA[2], jb.x, p);
        p = fma2(fA[3], jb.y, p);
        acc0 = fma2(p, pk2(d.x, d.x), acc0);

        unsigned long long q = mul2(fB[0], ja.x);
        q = fma2(fB[1], ja.y, q);
        q = fma2(fB[2], jb.x, q);
        q = fma2(fB[3], jb.y, q);
        acc1 = fma2(q, pk2(d.y, d.y), acc1);
    }

    float a0, a1, b0, b1;
    unpk2(acc0, a0, a1);
    unpk2(acc1, b0, b1);
    double dacc = ((double)a0 + (double)a1) + ((double)b0 + (double)b1);
    #pragma unroll
    for (int o = 16; o; o >>= 1)
        dacc += __shfl_xor_sync(0xffffffffu, dacc, o);
    if (lane == 0) s_red[wid] = dacc;
    __syncthreads();
    if (tid == 0) {
        double s = s_red[0];
        #pragma unroll
        for (int w = 1; w < 8; w++) s += s_red[w];
        g_part[bid] = s;
        __threadfence();
        s_last = (atomicAdd(&g_cnt_main, 1u) == (MAIN_BLKS - 1u));
    }
    __syncthreads();

    // ---- last block reduces all partials (fixed order -> deterministic) ----
    if (s_last) {
        double s = 0.0;
        for (int k = tid; k < MAIN_BLKS; k += 256)
            s += ((volatile double*)g_part)[k];
        #pragma unroll
        for (int o = 16; o; o >>= 1)
            s += __shfl_xor_sync(0xffffffffu, s, o);
        if (lane == 0) s_red[wid] = s;
        __syncthreads();
        if (tid == 0) {
            double t = s_red[0];
            #pragma unroll
            for (int w = 1; w < 8; w++) t += s_red[w];
            out[0] = (float)(t / 134217728.0);          // / (B*N*N)
            g_cnt_main = 0;                             // reset for graph replay
        }
    }
}

extern "C" void kernel_launch(void* const* d_in, const int* in_sizes, int n_in,
                              void* d_out, int out_size) {
    const float4* in4 = (const float4*)d_in[0];
    float*        out = (float*)d_out;

    k_pre<<<PRE_BLKS, 128>>>(in4);
    k_main<<<MAIN_BLKS, 256>>>(out);
}